// round 10
// baseline (speedup 1.0000x reference)
#include <cuda_runtime.h>
#include <cuda_bf16.h>
#include <cstdint>
#include <cstddef>

// Problem constants
#define WNUM  2048
#define NTOK  49
#define CDIM  256
#define HEADS 8
#define MROWS (WNUM * NTOK)   // 100352 = 784 * 128
#define KTOT  768             // split-K: [hi | lo | hi] x [hi | hi | lo]

// Static device scratch
__device__ float g_qkv[(size_t)MROWS * 768];
__device__ float g_cbias[64 * HEADS * NTOK * 50];     // layout [w][h][m][n-pad50]
__device__ float g_tbl[169 * HEADS];
__device__ float g_qkvb[768];
__device__ __nv_bfloat16 g_abig[(size_t)MROWS * KTOT];
__device__ __nv_bfloat16 g_bbq[768 * KTOT];
__device__ __nv_bfloat16 g_bbp[256 * KTOT];

// ---------------- helpers -----------------------------------------------------
__device__ __forceinline__ uint32_t smem_u32(const void* p) {
    uint32_t a;
    asm("{ .reg .u64 t; cvta.to.shared.u64 t, %1; cvt.u32.u64 %0, t; }" : "=r"(a) : "l"(p));
    return a;
}
__device__ __forceinline__ void cp_async16(uint32_t s, const void* g) {
    asm volatile("cp.async.ca.shared.global [%0], [%1], 16;" :: "r"(s), "l"(g));
}
#define CP_COMMIT() asm volatile("cp.async.commit_group;" ::: "memory")
#define CP_WAIT(n)  asm volatile("cp.async.wait_group %0;" :: "n"(n) : "memory")
#define LDMX4(r, a) asm volatile( \
    "ldmatrix.sync.aligned.m8n8.x4.shared.b16 {%0,%1,%2,%3}, [%4];" \
    : "=r"((r)[0]), "=r"((r)[1]), "=r"((r)[2]), "=r"((r)[3]) : "r"(a))
#define MMA16816(c, a, b0, b1) asm volatile( \
    "mma.sync.aligned.m16n8k16.row.col.f32.bf16.bf16.f32 " \
    "{%0,%1,%2,%3},{%4,%5,%6,%7},{%8,%9},{%0,%1,%2,%3};" \
    : "+f"((c)[0]), "+f"((c)[1]), "+f"((c)[2]), "+f"((c)[3]) \
    : "r"((a)[0]), "r"((a)[1]), "r"((a)[2]), "r"((a)[3]), "r"(b0), "r"(b1))

// XOR-swizzled 16B-chunk address within a [128][32]-bf16 tile (64B rows).
__device__ __forceinline__ uint32_t swz(int row, int chunk) {
    return (uint32_t)(row * 64 + ((chunk ^ ((row >> 1) & 3)) << 4));
}

// packed f32x2 (attention)
__device__ __forceinline__ unsigned long long pack2(float x, float y) {
    unsigned long long r;
    asm("mov.b64 %0, {%1, %2};" : "=l"(r) : "f"(x), "f"(y));
    return r;
}
__device__ __forceinline__ void unpack2(unsigned long long v, float& lo, float& hi) {
    asm("mov.b64 {%0, %1}, %2;" : "=f"(lo), "=f"(hi) : "l"(v));
}
__device__ __forceinline__ void ffma2(unsigned long long& d, unsigned long long a,
                                      unsigned long long b) {
    asm("fma.rn.f32x2 %0, %1, %2, %0;" : "+l"(d) : "l"(a), "l"(b));
}

// Fast exp on the FMA pipe (rel err ~2e-6). Avoids MUFU.
__device__ __forceinline__ float fexp(float x) {
    float y = fmaxf(x * 1.4426950408889634f, -126.0f);
    const int n = __float2int_rn(y);
    const float f = y - (float)n;
    float p = 1.3333558e-3f;
    p = fmaf(p, f, 9.6181291e-3f);
    p = fmaf(p, f, 5.5504109e-2f);
    p = fmaf(p, f, 2.4022651e-1f);
    p = fmaf(p, f, 6.9314718e-1f);
    p = fmaf(p, f, 1.0f);
    return p * __int_as_float((n + 127) << 23);
}

// ---------------- K1: CPB MLP table + qkv bias ----------------------------------
__global__ void prep_kernel(const float* __restrict__ rct, const float* __restrict__ w1,
                            const float* __restrict__ b1, const float* __restrict__ w2,
                            const float* __restrict__ qb, const float* __restrict__ vb)
{
    const int tid = threadIdx.x;
    for (int c = tid; c < 768; c += 256) {
        float v = 0.f;
        if (c < 256) v = qb[c];
        else if (c >= 512) v = vb[c - 512];
        g_qkvb[c] = v;
    }
    if (tid < 169) {
        const float t0 = rct[tid * 2 + 0];
        const float t1 = rct[tid * 2 + 1];
        float s[8] = {0.f, 0.f, 0.f, 0.f, 0.f, 0.f, 0.f, 0.f};
        for (int j = 0; j < 512; j++) {
            float hval = fmaf(t0, w1[j * 2 + 0], fmaf(t1, w1[j * 2 + 1], b1[j]));
            hval = fmaxf(hval, 0.f);
            #pragma unroll
            for (int h = 0; h < 8; h++) s[h] = fmaf(hval, w2[h * 512 + j], s[h]);
        }
        #pragma unroll
        for (int h = 0; h < 8; h++) g_tbl[tid * 8 + h] = s[h];
    }
}

// ---------------- K2a: weight planes [hi | hi | lo] -----------------------------
__global__ void __launch_bounds__(256) conv_w_kernel(
    const float* __restrict__ qkvw, const float* __restrict__ pw)
{
    const int i = blockIdx.x * 256 + threadIdx.x;
    if (i < 768 * 256) {
        const int n = i >> 8, k = i & 255;
        const float v = qkvw[i];
        const __nv_bfloat16 h = __float2bfloat16(v);
        const __nv_bfloat16 l = __float2bfloat16(v - __bfloat162float(h));
        __nv_bfloat16* row = g_bbq + (size_t)n * KTOT;
        row[k] = h; row[256 + k] = h; row[512 + k] = l;
    }
    const int j = i - 768 * 256;
    if (j >= 0 && j < 256 * 256) {
        const int n = j >> 8, k = j & 255;
        const float v = pw[j];
        const __nv_bfloat16 h = __float2bfloat16(v);
        const __nv_bfloat16 l = __float2bfloat16(v - __bfloat162float(h));
        __nv_bfloat16* row = g_bbp + (size_t)n * KTOT;
        row[k] = h; row[256 + k] = h; row[512 + k] = l;
    }
}

// ---------------- K2b: activation planes [hi | lo | hi] -------------------------
__global__ void __launch_bounds__(256) conv_a_kernel(const float* __restrict__ x)
{
    const int idx = blockIdx.x * 256 + threadIdx.x;   // MROWS*64
    const int m = idx >> 6, q = idx & 63;
    const float4 v = *(const float4*)(x + (size_t)m * 256 + q * 4);
    const __nv_bfloat162 h01 = __floats2bfloat162_rn(v.x, v.y);
    const __nv_bfloat162 h23 = __floats2bfloat162_rn(v.z, v.w);
    const __nv_bfloat162 l01 = __floats2bfloat162_rn(v.x - __bfloat162float(h01.x),
                                                     v.y - __bfloat162float(h01.y));
    const __nv_bfloat162 l23 = __floats2bfloat162_rn(v.z - __bfloat162float(h23.x),
                                                     v.w - __bfloat162float(h23.y));
    __nv_bfloat16* row = g_abig + (size_t)m * KTOT;
    *(__nv_bfloat162*)(row + q * 4)           = h01;
    *(__nv_bfloat162*)(row + q * 4 + 2)       = h23;
    *(__nv_bfloat162*)(row + 256 + q * 4)     = l01;
    *(__nv_bfloat162*)(row + 256 + q * 4 + 2) = l23;
    *(__nv_bfloat162*)(row + 512 + q * 4)     = h01;
    *(__nv_bfloat162*)(row + 512 + q * 4 + 2) = h23;
}

// ---------------- K3/K5: HMMA bf16 NT GEMM, 64x64 warp tile, 3-stage ------------
// 128 threads, 4 warps (2x2 of 64x64). One __syncthreads per K-iter.
// mode 0: B=g_bbq, bias=g_qkvb, C=g_qkv, N=768; tail blocks build the cbias table.
// mode 1: B=g_bbp, bias=param,  C=param, N=256
__global__ void __launch_bounds__(128, 2) gemm_mma(
    const float* __restrict__ biasp, float* __restrict__ Cp, int mode,
    const int* __restrict__ rpi, const float* __restrict__ mask)
{
    const int NX = mode ? 2 : 6;
    const int ngemm = NX * 784;
    const int gx = blockIdx.x;
    const int tid = threadIdx.x;

    if (gx >= ngemm) {   // cbias tail (mode 0 only): [w][h][m][n-pad50]
        const int i = (gx - ngemm) * 128 + tid;
        if (i < 64 * 8 * 49 * 50) {
            const int w   = i / (8 * 2450);
            const int rem = i - w * (8 * 2450);
            const int h   = rem / 2450;
            const int mn  = rem - h * 2450;
            const int m   = mn / 50;
            const int n   = mn - m * 50;
            float val = 0.f;
            if (n < 49) {
                const int nm = n * 49 + m;
                const float t = g_tbl[rpi[nm] * 8 + h];
                val = 16.f / (1.f + __expf(-t)) + mask[w * 2401 + nm];
            }
            g_cbias[i] = val;
        }
        return;
    }

    const __nv_bfloat16* A = g_abig;
    const __nv_bfloat16* B = mode ? g_bbp : g_bbq;
    const float* bias = mode ? biasp : g_qkvb;
    float* C = mode ? Cp : g_qkv;
    const int N = mode ? 256 : 768;

    __shared__ __nv_bfloat16 As[3][128][32];
    __shared__ __nv_bfloat16 Bs[3][128][32];

    const int lane = tid & 31, wid = tid >> 5;
    const int wm = wid >> 1, wn = wid & 1;
    const int m0 = (gx / NX) * 128, n0 = (gx % NX) * 128;
    const int lrow = tid >> 2, lseg = tid & 3;    // 32 rows x 4 chunks per pass

    const __nv_bfloat16* Ag = A + (size_t)(m0 + lrow) * KTOT + lseg * 8;
    const __nv_bfloat16* Bg = B + (size_t)(n0 + lrow) * KTOT + lseg * 8;

    float acc[4][8][4];
    #pragma unroll
    for (int i = 0; i < 4; i++)
        #pragma unroll
        for (int j = 0; j < 8; j++)
            #pragma unroll
            for (int r = 0; r < 4; r++) acc[i][j][r] = 0.f;

    auto load_tile = [&](int buf, int kt) {
        const __nv_bfloat16* ga = Ag + kt * 32;
        const __nv_bfloat16* gb = Bg + kt * 32;
        const uint32_t sA = smem_u32(&As[buf][0][0]);
        const uint32_t sB = smem_u32(&Bs[buf][0][0]);
        #pragma unroll
        for (int rr = 0; rr < 4; rr++) {
            cp_async16(sA + swz(lrow + rr * 32, lseg), ga + (size_t)(rr * 32) * KTOT);
            cp_async16(sB + swz(lrow + rr * 32, lseg), gb + (size_t)(rr * 32) * KTOT);
        }
        CP_COMMIT();
    };

    load_tile(0, 0);
    load_tile(1, 1);

    const int lr = lane & 15, lc = lane >> 4;
    const int NITER = KTOT / 32;   // 24

    int buf = 0;
    for (int kt = 0; kt < NITER; kt++) {
        if (kt + 1 < NITER) { CP_WAIT(1); } else { CP_WAIT(0); }
        __syncthreads();
        if (kt + 2 < NITER) {
            int nb = buf + 2; if (nb >= 3) nb -= 3;
            load_tile(nb, kt + 2);
        }
        const uint32_t sA = smem_u32(&As[buf][0][0]);
        const uint32_t sB = smem_u32(&Bs[buf][0][0]);
        #pragma unroll
        for (int kk = 0; kk < 2; kk++) {
            uint32_t af[4][4], bf[4][4];
            #pragma unroll
            for (int mi = 0; mi < 4; mi++)
                LDMX4(af[mi], sA + swz(wm * 64 + mi * 16 + lr, kk * 2 + lc));
            #pragma unroll
            for (int nj = 0; nj < 4; nj++)
                LDMX4(bf[nj], sB + swz(wn * 64 + nj * 16 + lr, kk * 2 + lc));
            #pragma unroll
            for (int mi = 0; mi < 4; mi++)
                #pragma unroll
                for (int nj = 0; nj < 4; nj++)
                    #pragma unroll
                    for (int hl = 0; hl < 2; hl++)
                        MMA16816(acc[mi][nj * 2 + hl], af[mi], bf[nj][hl], bf[nj][hl + 2]);
        }
        if (++buf >= 3) buf -= 3;
    }

    #pragma unroll
    for (int mi = 0; mi < 4; mi++) {
        #pragma unroll
        for (int nt = 0; nt < 8; nt++) {
            const int r = m0 + wm * 64 + mi * 16 + (lane >> 2);
            const int c = n0 + wn * 64 + nt * 8 + (lane & 3) * 2;
            const float b0 = bias[c], b1 = bias[c + 1];
            float* p0 = C + (size_t)r * N + c;
            float* p1 = C + (size_t)(r + 8) * N + c;
            p0[0] = acc[mi][nt][0] + b0;
            p0[1] = acc[mi][nt][1] + b1;
            p1[0] = acc[mi][nt][2] + b0;
            p1[1] = acc[mi][nt][3] + b1;
        }
    }
}

// ---------------- K4: window attention ------------------------------------------
// Thread = (query-pair, d-half): K/V smem reads amortized over 2 queries,
// partner-lane shfl combines the half-d partial dot products.
#define ATT_THREADS 224
#define ATT_SMEMF   (6272 + 6272 + 196 + 200 * 49)
__global__ void __launch_bounds__(ATT_THREADS, 2) attn_kernel(const float* __restrict__ logit_scale)
{
    extern __shared__ float sm[];
    float* Ks    = sm;
    float* Vs    = sm + 6272;
    float* Krs   = sm + 12544;
    float* arowb = sm + 12740;

    const int tid = threadIdx.x;
    const int b   = blockIdx.x >> 1;
    const int hb  = (blockIdx.x & 1) * 4;
    const size_t base = (size_t)b * NTOK * 768;

    {
        const float* gk = g_qkv + base + 256 + hb * 32;
        const float* gv = g_qkv + base + 512 + hb * 32;
        #pragma unroll
        for (int i = 0; i < 7; i++) {
            const int f = tid + i * ATT_THREADS;
            const int m = f >> 5, q = (f & 31) * 4;
            *(float4*)(Ks + m * 128 + q) = *(const float4*)(gk + (size_t)m * 768 + q);
            *(float4*)(Vs + m * 128 + q) = *(const float4*)(gv + (size_t)m * 768 + q);
        }
    }
    __syncthreads();

    if (tid < 196) {
        const int h = tid / NTOK, m = tid - (tid / NTOK) * NTOK;
        const float4* kp = (const float4*)(Ks + m * 128 + h * 32);
        float s0 = 0.f, s1 = 0.f, s2 = 0.f, s3 = 0.f;
        #pragma unroll
        for (int d = 0; d < 8; d++) {
            const float4 v = kp[d];
            s0 = fmaf(v.x, v.x, s0); s1 = fmaf(v.y, v.y, s1);
            s2 = fmaf(v.z, v.z, s2); s3 = fmaf(v.w, v.w, s3);
        }
        Krs[tid] = 1.0f / fmaxf(sqrtf((s0 + s1) + (s2 + s3)), 1e-12f);
    }
    __syncthreads();

    const int pair0 = tid >> 1;
    const int pair  = (pair0 < 100) ? pair0 : 99;
    const int dh    = tid & 1;
    const int h     = pair / 25;
    const int qp    = pair - h * 25;
    const int q0    = qp * 2;
    const int q1r   = (q0 + 1 < NTOK) ? q0 + 1 : NTOK - 1;
    const bool act  = (pair0 < 100);
    const bool v1   = act && (q0 + 1 < NTOK);
    const int hg    = hb + h;

    unsigned long long qq0[8], qq1[8];
    {
        const float4* qa = (const float4*)(g_qkv + base + (size_t)q0 * 768 + hg * 32 + dh * 16);
        const float4* qc = (const float4*)(g_qkv + base + (size_t)q1r * 768 + hg * 32 + dh * 16);
        float4 a[4], c[4];
        float s0 = 0.f, s1 = 0.f;
        #pragma unroll
        for (int d = 0; d < 4; d++) {
            a[d] = qa[d];
            s0 = fmaf(a[d].x, a[d].x, fmaf(a[d].y, a[d].y,
                 fmaf(a[d].z, a[d].z, fmaf(a[d].w, a[d].w, s0))));
            c[d] = qc[d];
            s1 = fmaf(c[d].x, c[d].x, fmaf(c[d].y, c[d].y,
                 fmaf(c[d].z, c[d].z, fmaf(c[d].w, c[d].w, s1))));
        }
        s0 += __shfl_xor_sync(0xFFFFFFFFu, s0, 1);
        s1 += __shfl_xor_sync(0xFFFFFFFFu, s1, 1);
        const float lsc = __expf(fminf(logit_scale[hg], 4.6051701859880914f));
        const float i0 = lsc / fmaxf(sqrtf(s0), 1e-12f);
        const float i1 = lsc / fmaxf(sqrtf(s1), 1e-12f);
        #pragma unroll
        for (int d = 0; d < 4; d++) {
            qq0[2 * d]     = pack2(a[d].x * i0, a[d].y * i0);
            qq0[2 * d + 1] = pack2(a[d].z * i0, a[d].w * i0);
            qq1[2 * d]     = pack2(c[d].x * i1, c[d].y * i1);
            qq1[2 * d + 1] = pack2(c[d].z * i1, c[d].w * i1);
        }
    }

    const float* krp = Krs + h * NTOK;
    const float* cbb = g_cbias + ((size_t)(b & 63) * 8 + hg) * (49 * 50) + q0;
    float* arow_own  = arowb + (pair * 2 + dh) * NTOK;

    float mx0 = -1e30f, mx1 = -1e30f;
    #pragma unroll 7
    for (int m = 0; m < NTOK; m++) {
        const ulonglong2* k4 = (const ulonglong2*)(Ks + m * 128 + h * 32 + dh * 16);
        unsigned long long a0 = 0ULL, a1 = 0ULL, c0 = 0ULL, c1 = 0ULL;
        #pragma unroll
        for (int j = 0; j < 2; j++) {
            const ulonglong2 kA = k4[2 * j], kB = k4[2 * j + 1];
            ffma2(a0, qq0[4 * j],     kA.x); ffma2(a1, qq0[4 * j + 1], kA.y);
            ffma2(a0, qq0[4 * j + 2], kB.x); ffma2(a1, qq0[4 * j + 3], kB.y);
            ffma2(c0, qq1[4 * j],     kA.x); ffma2(c1, qq1[4 * j + 1], kA.y);
            ffma2(c0, qq1[4 * j + 2], kB.x); ffma2(c1, qq1[4 * j + 3], kB.y);
        }
        float x0, x1, x2, x3;
        unpack2(a0, x0, x1); unpack2(a1, x2, x3);
        float p0 = (x0 + x1) + (x2 + x3);
        unpack2(c0, x0, x1); unpack2(c1, x2, x3);
        float p1 = (x0 + x1) + (x2 + x3);
        p0 += __shfl_xor_sync(0xFFFFFFFFu, p0, 1);
        p1 += __shfl_xor_sync(0xFFFFFFFFu, p1, 1);
        const float2 cb2 = *(const float2*)(cbb + m * 50);
        const float kr = krp[m];
        const float l0 = p0 * kr + cb2.x;
        const float l1 = p1 * kr + cb2.y;
        arow_own[m] = dh ? l1 : l0;
        mx0 = fmaxf(mx0, l0);
        mx1 = fmaxf(mx1, l1);
    }

    const float mxo = dh ? mx1 : mx0;
    float ss0 = 0.f, ss1 = 0.f;
    unsigned long long o20[8], o21[8];
    #pragma unroll
    for (int j = 0; j < 8; j++) { o20[j] = 0ULL; o21[j] = 0ULL; }
    #pragma unroll 7
    for (int m = 0; m < NTOK; m++) {
        const float eo = fexp(arow_own[m] - mxo);
        const float ex = __shfl_xor_sync(0xFFFFFFFFu, eo, 1);
        const float e0 = dh ? ex : eo;
        const float e1 = dh ? eo : ex;
        ss0 += e0; ss1 += e1;
        const ulonglong2* v4 = (const ulonglong2*)(Vs + m * 128 + h * 32 + dh * 16);
        const unsigned long long pp0 = pack2(e0, e0);
        const unsigned long long pp1 = pack2(e1, e1);
        #pragma unroll
        for (int j = 0; j < 2; j++) {
            const ulonglong2 vA = v4[2 * j], vB = v4[2 * j + 1];
            ffma2(o20[4 * j],     pp0, vA.x); ffma2(o20[4 * j + 1], pp0, vA.y);
            ffma2(o20[4 * j + 2], pp0, vB.x); ffma2(o20[4 * j + 3], pp0, vB.y);
            ffma2(o21[4 * j],     pp1, vA.x); ffma2(o21[4 * j + 1], pp1, vA.y);
            ffma2(o21[4 * j + 2], pp1, vB.x); ffma2(o21[4 * j + 3], pp1, vB.y);
        }
    }

    const float r0 = 1.0f / ss0;
    const float r1 = 1.0f / ss1;
    #pragma unroll
    for (int qi = 0; qi < 2; qi++) {
        const bool ok = qi ? v1 : act;
        if (!ok) continue;
        const unsigned long long* o2 = qi ? o21 : o20;
        const float rv = qi ? r1 : r0;
        const int q = q0 + qi;
        __nv_bfloat16* dst = g_abig + ((size_t)b * NTOK + q) * KTOT + hg * 32 + dh * 16;
        uint32_t hv[8], lv[8];
        #pragma unroll
        for (int j = 0; j < 8; j++) {
            float x0, x1;
            unpack2(o2[j], x0, x1);
            x0 *= rv; x1 *= rv;
            const __nv_bfloat162 hp = __floats2bfloat162_rn(x0, x1);
            const __nv_bfloat162 lp = __floats2bfloat162_rn(x0 - __bfloat162float(hp.x),
                                                            x1 - __bfloat162float(hp.y));
            hv[j] = *(const uint32_t*)&hp;
            lv[j] = *(const uint32_t*)&lp;
        }
        const uint4 H0 = make_uint4(hv[0], hv[1], hv[2], hv[3]);
        const uint4 H1 = make_uint4(hv[4], hv[5], hv[6], hv[7]);
        const uint4 L0 = make_uint4(lv[0], lv[1], lv[2], lv[3]);
        const uint4 L1 = make_uint4(lv[4], lv[5], lv[6], lv[7]);
        *(uint4*)(dst)           = H0;
        *(uint4*)(dst + 8)       = H1;
        *(uint4*)(dst + 256)     = L0;
        *(uint4*)(dst + 256 + 8) = L1;
        *(uint4*)(dst + 512)     = H0;
        *(uint4*)(dst + 512 + 8) = H1;
    }
}

// ---------------- launch ----------------------------------------------------------
extern "C" void kernel_launch(void* const* d_in, const int* in_sizes, int n_in,
                              void* d_out, int out_size)
{
    const float* x    = (const float*)d_in[0];
    const float* mask = (const float*)d_in[1];
    const float* qkvw = (const float*)d_in[2];
    const float* qb   = (const float*)d_in[3];
    const float* vb   = (const float*)d_in[4];
    const float* ls   = (const float*)d_in[5];
    const float* w1   = (const float*)d_in[6];
    const float* b1   = (const float*)d_in[7];
    const float* w2   = (const float*)d_in[8];
    const float* pw   = (const float*)d_in[9];
    const float* pb   = (const float*)d_in[10];
    const float* rct  = (const float*)d_in[11];
    const int*   rpi  = (const int*)d_in[12];
    float* out = (float*)d_out;

    const int attn_smem = ATT_SMEMF * 4;   // 90160 B
    cudaFuncSetAttribute(attn_kernel, cudaFuncAttributeMaxDynamicSharedMemorySize, attn_smem);

    const int nbias = (64 * 8 * 49 * 50 + 127) / 128;   // 7657 tail blocks

    prep_kernel<<<1, 256>>>(rct, w1, b1, w2, qb, vb);
    conv_w_kernel<<<1024, 256>>>(qkvw, pw);
    conv_a_kernel<<<25088, 256>>>(x);
    gemm_mma<<<6 * 784 + nbias, 128>>>(nullptr, nullptr, 0, rpi, mask);   // <- profiled
    attn_kernel<<<WNUM * 2, ATT_THREADS, attn_smem>>>(ls);
    gemm_mma<<<2 * 784, 128>>>(pb, out, 1, nullptr, nullptr);
}

// round 12
// speedup vs baseline: 1.5321x; 1.5321x over previous
#include <cuda_runtime.h>
#include <cuda_bf16.h>
#include <cstdint>
#include <cstddef>

// Problem constants
#define WNUM  2048
#define NTOK  49
#define CDIM  256
#define HEADS 8
#define MROWS (WNUM * NTOK)   // 100352 = 784 * 128
#define KTOT  768             // split-K: [hi | lo | hi] x [hi | hi | lo]

// Static device scratch
__device__ float g_qkv[(size_t)MROWS * 768];
__device__ float g_cbias[64 * HEADS * NTOK * 50];     // layout [w][h][m][n-pad50]
__device__ float g_tbl[169 * HEADS];
__device__ float g_qkvb[768];
__device__ __nv_bfloat16 g_abig[(size_t)MROWS * KTOT];
__device__ __nv_bfloat16 g_bbq[768 * KTOT];
__device__ __nv_bfloat16 g_bbp[256 * KTOT];

// ---------------- helpers -----------------------------------------------------
__device__ __forceinline__ uint32_t smem_u32(const void* p) {
    uint32_t a;
    asm("{ .reg .u64 t; cvta.to.shared.u64 t, %1; cvt.u32.u64 %0, t; }" : "=r"(a) : "l"(p));
    return a;
}
__device__ __forceinline__ void cp_async16(uint32_t s, const void* g) {
    asm volatile("cp.async.ca.shared.global [%0], [%1], 16;" :: "r"(s), "l"(g));
}
#define CP_COMMIT() asm volatile("cp.async.commit_group;" ::: "memory")
#define CP_WAIT(n)  asm volatile("cp.async.wait_group %0;" :: "n"(n) : "memory")
#define LDMX4(r, a) asm volatile( \
    "ldmatrix.sync.aligned.m8n8.x4.shared.b16 {%0,%1,%2,%3}, [%4];" \
    : "=r"((r)[0]), "=r"((r)[1]), "=r"((r)[2]), "=r"((r)[3]) : "r"(a))
#define MMA16816(c, a, b0, b1) asm volatile( \
    "mma.sync.aligned.m16n8k16.row.col.f32.bf16.bf16.f32 " \
    "{%0,%1,%2,%3},{%4,%5,%6,%7},{%8,%9},{%0,%1,%2,%3};" \
    : "+f"((c)[0]), "+f"((c)[1]), "+f"((c)[2]), "+f"((c)[3]) \
    : "r"((a)[0]), "r"((a)[1]), "r"((a)[2]), "r"((a)[3]), "r"(b0), "r"(b1))

// XOR-swizzled 16B-chunk address within a [128][32]-bf16 tile (64B rows).
__device__ __forceinline__ uint32_t swz(int row, int chunk) {
    return (uint32_t)(row * 64 + ((chunk ^ ((row >> 1) & 3)) << 4));
}

// packed f32x2 (attention)
__device__ __forceinline__ unsigned long long pack2(float x, float y) {
    unsigned long long r;
    asm("mov.b64 %0, {%1, %2};" : "=l"(r) : "f"(x), "f"(y));
    return r;
}
__device__ __forceinline__ void unpack2(unsigned long long v, float& lo, float& hi) {
    asm("mov.b64 {%0, %1}, %2;" : "=f"(lo), "=f"(hi) : "l"(v));
}
__device__ __forceinline__ void ffma2(unsigned long long& d, unsigned long long a,
                                      unsigned long long b) {
    asm("fma.rn.f32x2 %0, %1, %2, %0;" : "+l"(d) : "l"(a), "l"(b));
}

// Fast exp on the FMA pipe (rel err ~2e-6). Avoids MUFU.
__device__ __forceinline__ float fexp(float x) {
    float y = fmaxf(x * 1.4426950408889634f, -126.0f);
    const int n = __float2int_rn(y);
    const float f = y - (float)n;
    float p = 1.3333558e-3f;
    p = fmaf(p, f, 9.6181291e-3f);
    p = fmaf(p, f, 5.5504109e-2f);
    p = fmaf(p, f, 2.4022651e-1f);
    p = fmaf(p, f, 6.9314718e-1f);
    p = fmaf(p, f, 1.0f);
    return p * __int_as_float((n + 127) << 23);
}

// ---------------- K1: CPB MLP table + qkv bias ----------------------------------
__global__ void prep_kernel(const float* __restrict__ rct, const float* __restrict__ w1,
                            const float* __restrict__ b1, const float* __restrict__ w2,
                            const float* __restrict__ qb, const float* __restrict__ vb)
{
    const int tid = threadIdx.x;
    for (int c = tid; c < 768; c += 256) {
        float v = 0.f;
        if (c < 256) v = qb[c];
        else if (c >= 512) v = vb[c - 512];
        g_qkvb[c] = v;
    }
    if (tid < 169) {
        const float t0 = rct[tid * 2 + 0];
        const float t1 = rct[tid * 2 + 1];
        float s[8] = {0.f, 0.f, 0.f, 0.f, 0.f, 0.f, 0.f, 0.f};
        for (int j = 0; j < 512; j++) {
            float hval = fmaf(t0, w1[j * 2 + 0], fmaf(t1, w1[j * 2 + 1], b1[j]));
            hval = fmaxf(hval, 0.f);
            #pragma unroll
            for (int h = 0; h < 8; h++) s[h] = fmaf(hval, w2[h * 512 + j], s[h]);
        }
        #pragma unroll
        for (int h = 0; h < 8; h++) g_tbl[tid * 8 + h] = s[h];
    }
}

// ---------------- K2a: weight planes [hi | hi | lo] -----------------------------
__global__ void __launch_bounds__(256) conv_w_kernel(
    const float* __restrict__ qkvw, const float* __restrict__ pw)
{
    const int i = blockIdx.x * 256 + threadIdx.x;
    if (i < 768 * 256) {
        const int n = i >> 8, k = i & 255;
        const float v = qkvw[i];
        const __nv_bfloat16 h = __float2bfloat16(v);
        const __nv_bfloat16 l = __float2bfloat16(v - __bfloat162float(h));
        __nv_bfloat16* row = g_bbq + (size_t)n * KTOT;
        row[k] = h; row[256 + k] = h; row[512 + k] = l;
    }
    const int j = i - 768 * 256;
    if (j >= 0 && j < 256 * 256) {
        const int n = j >> 8, k = j & 255;
        const float v = pw[j];
        const __nv_bfloat16 h = __float2bfloat16(v);
        const __nv_bfloat16 l = __float2bfloat16(v - __bfloat162float(h));
        __nv_bfloat16* row = g_bbp + (size_t)n * KTOT;
        row[k] = h; row[256 + k] = h; row[512 + k] = l;
    }
}

// ---------------- K2b: activation planes [hi | lo | hi] -------------------------
__global__ void __launch_bounds__(256) conv_a_kernel(const float* __restrict__ x)
{
    const int idx = blockIdx.x * 256 + threadIdx.x;   // MROWS*64
    const int m = idx >> 6, q = idx & 63;
    const float4 v = *(const float4*)(x + (size_t)m * 256 + q * 4);
    const __nv_bfloat162 h01 = __floats2bfloat162_rn(v.x, v.y);
    const __nv_bfloat162 h23 = __floats2bfloat162_rn(v.z, v.w);
    const __nv_bfloat162 l01 = __floats2bfloat162_rn(v.x - __bfloat162float(h01.x),
                                                     v.y - __bfloat162float(h01.y));
    const __nv_bfloat162 l23 = __floats2bfloat162_rn(v.z - __bfloat162float(h23.x),
                                                     v.w - __bfloat162float(h23.y));
    __nv_bfloat16* row = g_abig + (size_t)m * KTOT;
    *(__nv_bfloat162*)(row + q * 4)           = h01;
    *(__nv_bfloat162*)(row + q * 4 + 2)       = h23;
    *(__nv_bfloat162*)(row + 256 + q * 4)     = l01;
    *(__nv_bfloat162*)(row + 256 + q * 4 + 2) = l23;
    *(__nv_bfloat162*)(row + 512 + q * 4)     = h01;
    *(__nv_bfloat162*)(row + 512 + q * 4 + 2) = h23;
}

// ---------------- K3/K5: HMMA bf16 NT GEMM (round-9 tile, 3-stage, 1 barrier) ---
// 256 threads, 8 warps (64x32 tiles). mode 0: N=768 + cbias tail; mode 1: N=256.
__global__ void __launch_bounds__(256, 2) gemm_mma(
    const float* __restrict__ biasp, float* __restrict__ Cp, int mode,
    const int* __restrict__ rpi, const float* __restrict__ mask)
{
    const int NX = mode ? 2 : 6;
    const int ngemm = NX * 784;
    const int gx = blockIdx.x;
    const int tid = threadIdx.x;

    if (gx >= ngemm) {   // cbias tail (mode 0 only): [w][h][m][n-pad50]
        const int i = (gx - ngemm) * 256 + tid;
        if (i < 64 * 8 * 49 * 50) {
            const int w   = i / (8 * 2450);
            const int rem = i - w * (8 * 2450);
            const int h   = rem / 2450;
            const int mn  = rem - h * 2450;
            const int m   = mn / 50;
            const int n   = mn - m * 50;
            float val = 0.f;
            if (n < 49) {
                const int nm = n * 49 + m;
                const float t = g_tbl[rpi[nm] * 8 + h];
                val = 16.f / (1.f + __expf(-t)) + mask[w * 2401 + nm];
            }
            g_cbias[i] = val;
        }
        return;
    }

    const __nv_bfloat16* A = g_abig;
    const __nv_bfloat16* B = mode ? g_bbp : g_bbq;
    const float* bias = mode ? biasp : g_qkvb;
    float* C = mode ? Cp : g_qkv;
    const int N = mode ? 256 : 768;

    __shared__ __nv_bfloat16 As[3][128][32];
    __shared__ __nv_bfloat16 Bs[3][128][32];

    const int lane = tid & 31, wid = tid >> 5;
    const int wm = wid >> 2, wn = wid & 3;
    const int m0 = (gx / NX) * 128, n0 = (gx % NX) * 128;
    const int lrow = tid >> 2, lseg = tid & 3;

    const __nv_bfloat16* Ag = A + (size_t)(m0 + lrow) * KTOT + lseg * 8;
    const __nv_bfloat16* Bg = B + (size_t)(n0 + lrow) * KTOT + lseg * 8;

    float acc[4][4][4];
    #pragma unroll
    for (int i = 0; i < 4; i++)
        #pragma unroll
        for (int j = 0; j < 4; j++)
            #pragma unroll
            for (int r = 0; r < 4; r++) acc[i][j][r] = 0.f;

    auto load_tile = [&](int buf, int kt) {
        const __nv_bfloat16* ga = Ag + kt * 32;
        const __nv_bfloat16* gb = Bg + kt * 32;
        const uint32_t sA = smem_u32(&As[buf][0][0]);
        const uint32_t sB = smem_u32(&Bs[buf][0][0]);
        cp_async16(sA + swz(lrow, lseg), ga);
        cp_async16(sA + swz(lrow + 64, lseg), ga + (size_t)64 * KTOT);
        cp_async16(sB + swz(lrow, lseg), gb);
        cp_async16(sB + swz(lrow + 64, lseg), gb + (size_t)64 * KTOT);
        CP_COMMIT();
    };

    load_tile(0, 0);
    load_tile(1, 1);

    const int lr = lane & 15, lc = lane >> 4;
    const int NITER = KTOT / 32;   // 24

    int buf = 0;
    for (int kt = 0; kt < NITER; kt++) {
        if (kt + 1 < NITER) { CP_WAIT(1); } else { CP_WAIT(0); }
        __syncthreads();
        if (kt + 2 < NITER) {
            int nb = buf + 2; if (nb >= 3) nb -= 3;
            load_tile(nb, kt + 2);
        }
        const uint32_t sA = smem_u32(&As[buf][0][0]);
        const uint32_t sB = smem_u32(&Bs[buf][0][0]);
        #pragma unroll
        for (int kk = 0; kk < 2; kk++) {
            uint32_t af[4][4], bf[2][4];
            #pragma unroll
            for (int mi = 0; mi < 4; mi++)
                LDMX4(af[mi], sA + swz(wm * 64 + mi * 16 + lr, kk * 2 + lc));
            #pragma unroll
            for (int nj = 0; nj < 2; nj++)
                LDMX4(bf[nj], sB + swz(wn * 32 + nj * 16 + lr, kk * 2 + lc));
            #pragma unroll
            for (int mi = 0; mi < 4; mi++)
                #pragma unroll
                for (int nt = 0; nt < 4; nt++) {
                    const uint32_t b0 = bf[nt >> 1][nt & 1];
                    const uint32_t b1 = bf[nt >> 1][(nt & 1) + 2];
                    MMA16816(acc[mi][nt], af[mi], b0, b1);
                }
        }
        if (++buf >= 3) buf -= 3;
    }

    #pragma unroll
    for (int mi = 0; mi < 4; mi++) {
        #pragma unroll
        for (int nt = 0; nt < 4; nt++) {
            const int r = m0 + wm * 64 + mi * 16 + (lane >> 2);
            const int c = n0 + wn * 32 + nt * 8 + (lane & 3) * 2;
            const float b0 = bias[c], b1 = bias[c + 1];
            float* p0 = C + (size_t)r * N + c;
            float* p1 = C + (size_t)(r + 8) * N + c;
            p0[0] = acc[mi][nt][0] + b0;
            p0[1] = acc[mi][nt][1] + b1;
            p1[0] = acc[mi][nt][2] + b0;
            p1[1] = acc[mi][nt][3] + b1;
        }
    }
}

// ---------------- K4: window attention ------------------------------------------
// Thread = (query-pair, d-half): K/V smem reads amortized over 2 queries,
// partner-lane shfl combines the half-d partial dot products.
#define ATT_THREADS 224
#define ATT_SMEMF   (6272 + 6272 + 196 + 200 * 49)
__global__ void __launch_bounds__(ATT_THREADS, 2) attn_kernel(const float* __restrict__ logit_scale)
{
    extern __shared__ float sm[];
    float* Ks    = sm;
    float* Vs    = sm + 6272;
    float* Krs   = sm + 12544;
    float* arowb = sm + 12740;

    const int tid = threadIdx.x;
    const int b   = blockIdx.x >> 1;
    const int hb  = (blockIdx.x & 1) * 4;
    const size_t base = (size_t)b * NTOK * 768;

    {
        const float* gk = g_qkv + base + 256 + hb * 32;
        const float* gv = g_qkv + base + 512 + hb * 32;
        #pragma unroll
        for (int i = 0; i < 7; i++) {
            const int f = tid + i * ATT_THREADS;
            const int m = f >> 5, q = (f & 31) * 4;
            *(float4*)(Ks + m * 128 + q) = *(const float4*)(gk + (size_t)m * 768 + q);
            *(float4*)(Vs + m * 128 + q) = *(const float4*)(gv + (size_t)m * 768 + q);
        }
    }
    __syncthreads();

    if (tid < 196) {
        const int h = tid / NTOK, m = tid - (tid / NTOK) * NTOK;
        const float4* kp = (const float4*)(Ks + m * 128 + h * 32);
        float s0 = 0.f, s1 = 0.f, s2 = 0.f, s3 = 0.f;
        #pragma unroll
        for (int d = 0; d < 8; d++) {
            const float4 v = kp[d];
            s0 = fmaf(v.x, v.x, s0); s1 = fmaf(v.y, v.y, s1);
            s2 = fmaf(v.z, v.z, s2); s3 = fmaf(v.w, v.w, s3);
        }
        Krs[tid] = 1.0f / fmaxf(sqrtf((s0 + s1) + (s2 + s3)), 1e-12f);
    }
    __syncthreads();

    const int pair0 = tid >> 1;
    const int pair  = (pair0 < 100) ? pair0 : 99;
    const int dh    = tid & 1;
    const int h     = pair / 25;
    const int qp    = pair - h * 25;
    const int q0    = qp * 2;
    const int q1r   = (q0 + 1 < NTOK) ? q0 + 1 : NTOK - 1;
    const bool act  = (pair0 < 100);
    const bool v1   = act && (q0 + 1 < NTOK);
    const int hg    = hb + h;

    unsigned long long qq0[8], qq1[8];
    {
        const float4* qa = (const float4*)(g_qkv + base + (size_t)q0 * 768 + hg * 32 + dh * 16);
        const float4* qc = (const float4*)(g_qkv + base + (size_t)q1r * 768 + hg * 32 + dh * 16);
        float4 a[4], c[4];
        float s0 = 0.f, s1 = 0.f;
        #pragma unroll
        for (int d = 0; d < 4; d++) {
            a[d] = qa[d];
            s0 = fmaf(a[d].x, a[d].x, fmaf(a[d].y, a[d].y,
                 fmaf(a[d].z, a[d].z, fmaf(a[d].w, a[d].w, s0))));
            c[d] = qc[d];
            s1 = fmaf(c[d].x, c[d].x, fmaf(c[d].y, c[d].y,
                 fmaf(c[d].z, c[d].z, fmaf(c[d].w, c[d].w, s1))));
        }
        s0 += __shfl_xor_sync(0xFFFFFFFFu, s0, 1);
        s1 += __shfl_xor_sync(0xFFFFFFFFu, s1, 1);
        const float lsc = __expf(fminf(logit_scale[hg], 4.6051701859880914f));
        const float i0 = lsc / fmaxf(sqrtf(s0), 1e-12f);
        const float i1 = lsc / fmaxf(sqrtf(s1), 1e-12f);
        #pragma unroll
        for (int d = 0; d < 4; d++) {
            qq0[2 * d]     = pack2(a[d].x * i0, a[d].y * i0);
            qq0[2 * d + 1] = pack2(a[d].z * i0, a[d].w * i0);
            qq1[2 * d]     = pack2(c[d].x * i1, c[d].y * i1);
            qq1[2 * d + 1] = pack2(c[d].z * i1, c[d].w * i1);
        }
    }

    const float* krp = Krs + h * NTOK;
    const float* cbb = g_cbias + ((size_t)(b & 63) * 8 + hg) * (49 * 50) + q0;
    float* arow_own  = arowb + (pair * 2 + dh) * NTOK;

    float mx0 = -1e30f, mx1 = -1e30f;
    #pragma unroll 7
    for (int m = 0; m < NTOK; m++) {
        const ulonglong2* k4 = (const ulonglong2*)(Ks + m * 128 + h * 32 + dh * 16);
        unsigned long long a0 = 0ULL, a1 = 0ULL, c0 = 0ULL, c1 = 0ULL;
        #pragma unroll
        for (int j = 0; j < 2; j++) {
            const ulonglong2 kA = k4[2 * j], kB = k4[2 * j + 1];
            ffma2(a0, qq0[4 * j],     kA.x); ffma2(a1, qq0[4 * j + 1], kA.y);
            ffma2(a0, qq0[4 * j + 2], kB.x); ffma2(a1, qq0[4 * j + 3], kB.y);
            ffma2(c0, qq1[4 * j],     kA.x); ffma2(c1, qq1[4 * j + 1], kA.y);
            ffma2(c0, qq1[4 * j + 2], kB.x); ffma2(c1, qq1[4 * j + 3], kB.y);
        }
        float x0, x1, x2, x3;
        unpack2(a0, x0, x1); unpack2(a1, x2, x3);
        float p0 = (x0 + x1) + (x2 + x3);
        unpack2(c0, x0, x1); unpack2(c1, x2, x3);
        float p1 = (x0 + x1) + (x2 + x3);
        p0 += __shfl_xor_sync(0xFFFFFFFFu, p0, 1);
        p1 += __shfl_xor_sync(0xFFFFFFFFu, p1, 1);
        const float2 cb2 = *(const float2*)(cbb + m * 50);
        const float kr = krp[m];
        const float l0 = p0 * kr + cb2.x;
        const float l1 = p1 * kr + cb2.y;
        arow_own[m] = dh ? l1 : l0;
        mx0 = fmaxf(mx0, l0);
        mx1 = fmaxf(mx1, l1);
    }

    const float mxo = dh ? mx1 : mx0;
    float ss0 = 0.f, ss1 = 0.f;
    unsigned long long o20[8], o21[8];
    #pragma unroll
    for (int j = 0; j < 8; j++) { o20[j] = 0ULL; o21[j] = 0ULL; }
    #pragma unroll 7
    for (int m = 0; m < NTOK; m++) {
        const float eo = fexp(arow_own[m] - mxo);
        const float ex = __shfl_xor_sync(0xFFFFFFFFu, eo, 1);
        const float e0 = dh ? ex : eo;
        const float e1 = dh ? eo : ex;
        ss0 += e0; ss1 += e1;
        const ulonglong2* v4 = (const ulonglong2*)(Vs + m * 128 + h * 32 + dh * 16);
        const unsigned long long pp0 = pack2(e0, e0);
        const unsigned long long pp1 = pack2(e1, e1);
        #pragma unroll
        for (int j = 0; j < 2; j++) {
            const ulonglong2 vA = v4[2 * j], vB = v4[2 * j + 1];
            ffma2(o20[4 * j],     pp0, vA.x); ffma2(o20[4 * j + 1], pp0, vA.y);
            ffma2(o20[4 * j + 2], pp0, vB.x); ffma2(o20[4 * j + 3], pp0, vB.y);
            ffma2(o21[4 * j],     pp1, vA.x); ffma2(o21[4 * j + 1], pp1, vA.y);
            ffma2(o21[4 * j + 2], pp1, vB.x); ffma2(o21[4 * j + 3], pp1, vB.y);
        }
    }

    const float r0 = 1.0f / ss0;
    const float r1 = 1.0f / ss1;
    #pragma unroll
    for (int qi = 0; qi < 2; qi++) {
        const bool ok = qi ? v1 : act;
        if (!ok) continue;
        const unsigned long long* o2 = qi ? o21 : o20;
        const float rv = qi ? r1 : r0;
        const int q = q0 + qi;
        __nv_bfloat16* dst = g_abig + ((size_t)b * NTOK + q) * KTOT + hg * 32 + dh * 16;
        uint32_t hv[8], lv[8];
        #pragma unroll
        for (int j = 0; j < 8; j++) {
            float x0, x1;
            unpack2(o2[j], x0, x1);
            x0 *= rv; x1 *= rv;
            const __nv_bfloat162 hp = __floats2bfloat162_rn(x0, x1);
            const __nv_bfloat162 lp = __floats2bfloat162_rn(x0 - __bfloat162float(hp.x),
                                                            x1 - __bfloat162float(hp.y));
            hv[j] = *(const uint32_t*)&hp;
            lv[j] = *(const uint32_t*)&lp;
        }
        const uint4 H0 = make_uint4(hv[0], hv[1], hv[2], hv[3]);
        const uint4 H1 = make_uint4(hv[4], hv[5], hv[6], hv[7]);
        const uint4 L0 = make_uint4(lv[0], lv[1], lv[2], lv[3]);
        const uint4 L1 = make_uint4(lv[4], lv[5], lv[6], lv[7]);
        *(uint4*)(dst)           = H0;
        *(uint4*)(dst + 8)       = H1;
        *(uint4*)(dst + 256)     = L0;
        *(uint4*)(dst + 256 + 8) = L1;
        *(uint4*)(dst + 512)     = H0;
        *(uint4*)(dst + 512 + 8) = H1;
    }
}

// ---------------- launch ----------------------------------------------------------
extern "C" void kernel_launch(void* const* d_in, const int* in_sizes, int n_in,
                              void* d_out, int out_size)
{
    const float* x    = (const float*)d_in[0];
    const float* mask = (const float*)d_in[1];
    const float* qkvw = (const float*)d_in[2];
    const float* qb   = (const float*)d_in[3];
    const float* vb   = (const float*)d_in[4];
    const float* ls   = (const float*)d_in[5];
    const float* w1   = (const float*)d_in[6];
    const float* b1   = (const float*)d_in[7];
    const float* w2   = (const float*)d_in[8];
    const float* pw   = (const float*)d_in[9];
    const float* pb   = (const float*)d_in[10];
    const float* rct  = (const float*)d_in[11];
    const int*   rpi  = (const int*)d_in[12];
    float* out = (float*)d_out;

    const int attn_smem = ATT_SMEMF * 4;   // 90160 B
    cudaFuncSetAttribute(attn_kernel, cudaFuncAttributeMaxDynamicSharedMemorySize, attn_smem);

    const int nbias = (64 * 8 * 49 * 50 + 255) / 256;   // 3829 tail blocks

    prep_kernel<<<1, 256>>>(rct, w1, b1, w2, qb, vb);
    conv_w_kernel<<<1024, 256>>>(qkvw, pw);
    conv_a_kernel<<<25088, 256>>>(x);
    gemm_mma<<<6 * 784 + nbias, 256>>>(nullptr, nullptr, 0, rpi, mask);   // <- profiled
    attn_kernel<<<WNUM * 2, ATT_THREADS, attn_smem>>>(ls);
    gemm_mma<<<2 * 784, 256>>>(pb, out, 1, nullptr, nullptr);
}

// round 15
// speedup vs baseline: 1.8597x; 1.2138x over previous
#include <cuda_runtime.h>
#include <cuda_fp16.h>
#include <cstdint>
#include <cstddef>

// Problem constants
#define WNUM  2048
#define NTOK  49
#define CDIM  256
#define HEADS 8
#define MROWS (WNUM * NTOK)   // 100352 = 784 * 128
#define KTOT  512             // fp16 2-plane: A=[hi|lo], B=[hi|hi]

// Static device scratch
__device__ float g_qkv[(size_t)MROWS * 768];
__device__ float g_cbias[64 * HEADS * NTOK * 50];     // layout [w][h][m][n-pad50]
__device__ float g_tbl[169 * HEADS];
__device__ float g_qkvb[768];
__device__ __half g_abig[(size_t)MROWS * KTOT];
__device__ __half g_bbq[768 * KTOT];
__device__ __half g_bbp[256 * KTOT];

// ---------------- helpers -----------------------------------------------------
__device__ __forceinline__ uint32_t smem_u32(const void* p) {
    uint32_t a;
    asm("{ .reg .u64 t; cvta.to.shared.u64 t, %1; cvt.u32.u64 %0, t; }" : "=r"(a) : "l"(p));
    return a;
}
__device__ __forceinline__ void cp_async16(uint32_t s, const void* g) {
    asm volatile("cp.async.ca.shared.global [%0], [%1], 16;" :: "r"(s), "l"(g));
}
#define CP_COMMIT() asm volatile("cp.async.commit_group;" ::: "memory")
#define CP_WAIT(n)  asm volatile("cp.async.wait_group %0;" :: "n"(n) : "memory")
#define LDMX4(r, a) asm volatile( \
    "ldmatrix.sync.aligned.m8n8.x4.shared.b16 {%0,%1,%2,%3}, [%4];" \
    : "=r"((r)[0]), "=r"((r)[1]), "=r"((r)[2]), "=r"((r)[3]) : "r"(a))
#define MMA16816(c, a, b0, b1) asm volatile( \
    "mma.sync.aligned.m16n8k16.row.col.f32.f16.f16.f32 " \
    "{%0,%1,%2,%3},{%4,%5,%6,%7},{%8,%9},{%0,%1,%2,%3};" \
    : "+f"((c)[0]), "+f"((c)[1]), "+f"((c)[2]), "+f"((c)[3]) \
    : "r"((a)[0]), "r"((a)[1]), "r"((a)[2]), "r"((a)[3]), "r"(b0), "r"(b1))

// XOR-swizzled 16B-chunk address within a [128][32]-half tile (64B rows).
__device__ __forceinline__ uint32_t swz(int row, int chunk) {
    return (uint32_t)(row * 64 + ((chunk ^ ((row >> 1) & 3)) << 4));
}

// packed f32x2 (attention)
__device__ __forceinline__ unsigned long long pack2(float x, float y) {
    unsigned long long r;
    asm("mov.b64 %0, {%1, %2};" : "=l"(r) : "f"(x), "f"(y));
    return r;
}
__device__ __forceinline__ void unpack2(unsigned long long v, float& lo, float& hi) {
    asm("mov.b64 {%0, %1}, %2;" : "=f"(lo), "=f"(hi) : "l"(v));
}
__device__ __forceinline__ void ffma2(unsigned long long& d, unsigned long long a,
                                      unsigned long long b) {
    asm("fma.rn.f32x2 %0, %1, %2, %0;" : "+l"(d) : "l"(a), "l"(b));
}

// Fast exp on the FMA pipe (rel err ~2e-6). Avoids MUFU.
__device__ __forceinline__ float fexp(float x) {
    float y = fmaxf(x * 1.4426950408889634f, -126.0f);
    const int n = __float2int_rn(y);
    const float f = y - (float)n;
    float p = 1.3333558e-3f;
    p = fmaf(p, f, 9.6181291e-3f);
    p = fmaf(p, f, 5.5504109e-2f);
    p = fmaf(p, f, 2.4022651e-1f);
    p = fmaf(p, f, 6.9314718e-1f);
    p = fmaf(p, f, 1.0f);
    return p * __int_as_float((n + 127) << 23);
}

// ---------------- K1: CPB MLP table + qkv bias ----------------------------------
__global__ void prep_kernel(const float* __restrict__ rct, const float* __restrict__ w1,
                            const float* __restrict__ b1, const float* __restrict__ w2,
                            const float* __restrict__ qb, const float* __restrict__ vb)
{
    const int tid = threadIdx.x;
    for (int c = tid; c < 768; c += 256) {
        float v = 0.f;
        if (c < 256) v = qb[c];
        else if (c >= 512) v = vb[c - 512];
        g_qkvb[c] = v;
    }
    if (tid < 169) {
        const float t0 = rct[tid * 2 + 0];
        const float t1 = rct[tid * 2 + 1];
        float s[8] = {0.f, 0.f, 0.f, 0.f, 0.f, 0.f, 0.f, 0.f};
        for (int j = 0; j < 512; j++) {
            float hval = fmaf(t0, w1[j * 2 + 0], fmaf(t1, w1[j * 2 + 1], b1[j]));
            hval = fmaxf(hval, 0.f);
            #pragma unroll
            for (int h = 0; h < 8; h++) s[h] = fmaf(hval, w2[h * 512 + j], s[h]);
        }
        #pragma unroll
        for (int h = 0; h < 8; h++) g_tbl[tid * 8 + h] = s[h];
    }
}

// ---------------- K2a: weight planes [hi | hi] (fp16) ---------------------------
__global__ void __launch_bounds__(256) conv_w_kernel(
    const float* __restrict__ qkvw, const float* __restrict__ pw)
{
    const int i = blockIdx.x * 256 + threadIdx.x;
    if (i < 768 * 256) {
        const int n = i >> 8, k = i & 255;
        const __half h = __float2half_rn(qkvw[i]);
        __half* row = g_bbq + (size_t)n * KTOT;
        row[k] = h; row[256 + k] = h;
    }
    const int j = i - 768 * 256;
    if (j >= 0 && j < 256 * 256) {
        const int n = j >> 8, k = j & 255;
        const __half h = __float2half_rn(pw[j]);
        __half* row = g_bbp + (size_t)n * KTOT;
        row[k] = h; row[256 + k] = h;
    }
}

// ---------------- K2b: activation planes [hi | lo] (fp16) -----------------------
__global__ void __launch_bounds__(256) conv_a_kernel(const float* __restrict__ x)
{
    const int idx = blockIdx.x * 256 + threadIdx.x;   // MROWS*64
    const int m = idx >> 6, q = idx & 63;
    const float4 v = *(const float4*)(x + (size_t)m * 256 + q * 4);
    const __half h0 = __float2half_rn(v.x), h1 = __float2half_rn(v.y);
    const __half h2 = __float2half_rn(v.z), h3 = __float2half_rn(v.w);
    const __half l0 = __float2half_rn(v.x - __half2float(h0));
    const __half l1 = __float2half_rn(v.y - __half2float(h1));
    const __half l2 = __float2half_rn(v.z - __half2float(h2));
    const __half l3 = __float2half_rn(v.w - __half2float(h3));
    __half* row = g_abig + (size_t)m * KTOT;
    *(__half2*)(row + q * 4)           = __halves2half2(h0, h1);
    *(__half2*)(row + q * 4 + 2)       = __halves2half2(h2, h3);
    *(__half2*)(row + 256 + q * 4)     = __halves2half2(l0, l1);
    *(__half2*)(row + 256 + q * 4 + 2) = __halves2half2(l2, l3);
}

// ---------------- K3/K5: HMMA fp16 NT GEMM (K'=512, 3-stage) --------------------
// 256 threads, 8 warps (64x32 tiles). mode 0: N=768 + cbias tail; mode 1: N=256.
__global__ void __launch_bounds__(256, 2) gemm_mma(
    const float* __restrict__ biasp, float* __restrict__ Cp, int mode,
    const int* __restrict__ rpi, const float* __restrict__ mask)
{
    const int NX = mode ? 2 : 6;
    const int ngemm = NX * 784;
    const int gx = blockIdx.x;
    const int tid = threadIdx.x;

    if (gx >= ngemm) {   // cbias tail (mode 0 only): [w][h][m][n-pad50]
        const int i = (gx - ngemm) * 256 + tid;
        if (i < 64 * 8 * 49 * 50) {
            const int w   = i / (8 * 2450);
            const int rem = i - w * (8 * 2450);
            const int h   = rem / 2450;
            const int mn  = rem - h * 2450;
            const int m   = mn / 50;
            const int n   = mn - m * 50;
            float val = 0.f;
            if (n < 49) {
                const int nm = n * 49 + m;
                const float t = g_tbl[rpi[nm] * 8 + h];
                val = 16.f / (1.f + __expf(-t)) + mask[w * 2401 + nm];
            }
            g_cbias[i] = val;
        }
        return;
    }

    const __half* A = g_abig;
    const __half* B = mode ? g_bbp : g_bbq;
    const float* bias = mode ? biasp : g_qkvb;
    float* C = mode ? Cp : g_qkv;
    const int N = mode ? 256 : 768;

    __shared__ __half As[3][128][32];
    __shared__ __half Bs[3][128][32];

    const int lane = tid & 31, wid = tid >> 5;
    const int wm = wid >> 2, wn = wid & 3;
    const int m0 = (gx / NX) * 128, n0 = (gx % NX) * 128;
    const int lrow = tid >> 2, lseg = tid & 3;

    const __half* Ag = A + (size_t)(m0 + lrow) * KTOT + lseg * 8;
    const __half* Bg = B + (size_t)(n0 + lrow) * KTOT + lseg * 8;

    float acc[4][4][4];
    #pragma unroll
    for (int i = 0; i < 4; i++)
        #pragma unroll
        for (int j = 0; j < 4; j++)
            #pragma unroll
            for (int r = 0; r < 4; r++) acc[i][j][r] = 0.f;

    auto load_tile = [&](int buf, int kt) {
        const __half* ga = Ag + kt * 32;
        const __half* gb = Bg + kt * 32;
        const uint32_t sA = smem_u32(&As[buf][0][0]);
        const uint32_t sB = smem_u32(&Bs[buf][0][0]);
        cp_async16(sA + swz(lrow, lseg), ga);
        cp_async16(sA + swz(lrow + 64, lseg), ga + (size_t)64 * KTOT);
        cp_async16(sB + swz(lrow, lseg), gb);
        cp_async16(sB + swz(lrow + 64, lseg), gb + (size_t)64 * KTOT);
        CP_COMMIT();
    };

    load_tile(0, 0);
    load_tile(1, 1);

    const int lr = lane & 15, lc = lane >> 4;
    const int NITER = KTOT / 32;   // 16

    int buf = 0;
    for (int kt = 0; kt < NITER; kt++) {
        if (kt + 1 < NITER) { CP_WAIT(1); } else { CP_WAIT(0); }
        __syncthreads();
        if (kt + 2 < NITER) {
            int nb = buf + 2; if (nb >= 3) nb -= 3;
            load_tile(nb, kt + 2);
        }
        const uint32_t sA = smem_u32(&As[buf][0][0]);
        const uint32_t sB = smem_u32(&Bs[buf][0][0]);
        #pragma unroll
        for (int kk = 0; kk < 2; kk++) {
            uint32_t af[4][4], bf[2][4];
            #pragma unroll
            for (int mi = 0; mi < 4; mi++)
                LDMX4(af[mi], sA + swz(wm * 64 + mi * 16 + lr, kk * 2 + lc));
            #pragma unroll
            for (int nj = 0; nj < 2; nj++)
                LDMX4(bf[nj], sB + swz(wn * 32 + nj * 16 + lr, kk * 2 + lc));
            #pragma unroll
            for (int mi = 0; mi < 4; mi++)
                #pragma unroll
                for (int nt = 0; nt < 4; nt++) {
                    const uint32_t b0 = bf[nt >> 1][nt & 1];
                    const uint32_t b1 = bf[nt >> 1][(nt & 1) + 2];
                    MMA16816(acc[mi][nt], af[mi], b0, b1);
                }
        }
        if (++buf >= 3) buf -= 3;
    }

    #pragma unroll
    for (int mi = 0; mi < 4; mi++) {
        #pragma unroll
        for (int nt = 0; nt < 4; nt++) {
            const int r = m0 + wm * 64 + mi * 16 + (lane >> 2);
            const int c = n0 + wn * 32 + nt * 8 + (lane & 3) * 2;
            const float b0 = bias[c], b1 = bias[c + 1];
            float* p0 = C + (size_t)r * N + c;
            float* p1 = C + (size_t)(r + 8) * N + c;
            p0[0] = acc[mi][nt][0] + b0;
            p0[1] = acc[mi][nt][1] + b1;
            p1[0] = acc[mi][nt][2] + b0;
            p1[1] = acc[mi][nt][3] + b1;
        }
    }
}

// ---------------- K4: window attention ------------------------------------------
// Thread = (query-pair, d-half): K/V smem reads amortized over 2 queries,
// partner-lane shfl combines the half-d partial dot products.
#define ATT_THREADS 224
#define ATT_SMEMF   (6272 + 6272 + 196 + 200 * 49)
__global__ void __launch_bounds__(ATT_THREADS, 2) attn_kernel(const float* __restrict__ logit_scale)
{
    extern __shared__ float sm[];
    float* Ks    = sm;
    float* Vs    = sm + 6272;
    float* Krs   = sm + 12544;
    float* arowb = sm + 12740;

    const int tid = threadIdx.x;
    const int b   = blockIdx.x >> 1;
    const int hb  = (blockIdx.x & 1) * 4;
    const size_t base = (size_t)b * NTOK * 768;

    {
        const float* gk = g_qkv + base + 256 + hb * 32;
        const float* gv = g_qkv + base + 512 + hb * 32;
        #pragma unroll
        for (int i = 0; i < 7; i++) {
            const int f = tid + i * ATT_THREADS;
            const int m = f >> 5, q = (f & 31) * 4;
            *(float4*)(Ks + m * 128 + q) = *(const float4*)(gk + (size_t)m * 768 + q);
            *(float4*)(Vs + m * 128 + q) = *(const float4*)(gv + (size_t)m * 768 + q);
        }
    }
    __syncthreads();

    if (tid < 196) {
        const int h = tid / NTOK, m = tid - (tid / NTOK) * NTOK;
        const float4* kp = (const float4*)(Ks + m * 128 + h * 32);
        float s0 = 0.f, s1 = 0.f, s2 = 0.f, s3 = 0.f;
        #pragma unroll
        for (int d = 0; d < 8; d++) {
            const float4 v = kp[d];
            s0 = fmaf(v.x, v.x, s0); s1 = fmaf(v.y, v.y, s1);
            s2 = fmaf(v.z, v.z, s2); s3 = fmaf(v.w, v.w, s3);
        }
        Krs[tid] = 1.0f / fmaxf(sqrtf((s0 + s1) + (s2 + s3)), 1e-12f);
    }
    __syncthreads();

    const int pair0 = tid >> 1;
    const int pair  = (pair0 < 100) ? pair0 : 99;
    const int dh    = tid & 1;
    const int h     = pair / 25;
    const int qp    = pair - h * 25;
    const int q0    = qp * 2;
    const int q1r   = (q0 + 1 < NTOK) ? q0 + 1 : NTOK - 1;
    const bool act  = (pair0 < 100);
    const bool v1   = act && (q0 + 1 < NTOK);
    const int hg    = hb + h;

    unsigned long long qq0[8], qq1[8];
    {
        const float4* qa = (const float4*)(g_qkv + base + (size_t)q0 * 768 + hg * 32 + dh * 16);
        const float4* qc = (const float4*)(g_qkv + base + (size_t)q1r * 768 + hg * 32 + dh * 16);
        float4 a[4], c[4];
        float s0 = 0.f, s1 = 0.f;
        #pragma unroll
        for (int d = 0; d < 4; d++) {
            a[d] = qa[d];
            s0 = fmaf(a[d].x, a[d].x, fmaf(a[d].y, a[d].y,
                 fmaf(a[d].z, a[d].z, fmaf(a[d].w, a[d].w, s0))));
            c[d] = qc[d];
            s1 = fmaf(c[d].x, c[d].x, fmaf(c[d].y, c[d].y,
                 fmaf(c[d].z, c[d].z, fmaf(c[d].w, c[d].w, s1))));
        }
        s0 += __shfl_xor_sync(0xFFFFFFFFu, s0, 1);
        s1 += __shfl_xor_sync(0xFFFFFFFFu, s1, 1);
        const float lsc = __expf(fminf(logit_scale[hg], 4.6051701859880914f));
        const float i0 = lsc / fmaxf(sqrtf(s0), 1e-12f);
        const float i1 = lsc / fmaxf(sqrtf(s1), 1e-12f);
        #pragma unroll
        for (int d = 0; d < 4; d++) {
            qq0[2 * d]     = pack2(a[d].x * i0, a[d].y * i0);
            qq0[2 * d + 1] = pack2(a[d].z * i0, a[d].w * i0);
            qq1[2 * d]     = pack2(c[d].x * i1, c[d].y * i1);
            qq1[2 * d + 1] = pack2(c[d].z * i1, c[d].w * i1);
        }
    }

    const float* krp = Krs + h * NTOK;
    const float* cbb = g_cbias + ((size_t)(b & 63) * 8 + hg) * (49 * 50) + q0;
    float* arow_own  = arowb + (pair * 2 + dh) * NTOK;

    float mx0 = -1e30f, mx1 = -1e30f;
    #pragma unroll 7
    for (int m = 0; m < NTOK; m++) {
        const ulonglong2* k4 = (const ulonglong2*)(Ks + m * 128 + h * 32 + dh * 16);
        unsigned long long a0 = 0ULL, a1 = 0ULL, c0 = 0ULL, c1 = 0ULL;
        #pragma unroll
        for (int j = 0; j < 2; j++) {
            const ulonglong2 kA = k4[2 * j], kB = k4[2 * j + 1];
            ffma2(a0, qq0[4 * j],     kA.x); ffma2(a1, qq0[4 * j + 1], kA.y);
            ffma2(a0, qq0[4 * j + 2], kB.x); ffma2(a1, qq0[4 * j + 3], kB.y);
            ffma2(c0, qq1[4 * j],     kA.x); ffma2(c1, qq1[4 * j + 1], kA.y);
            ffma2(c0, qq1[4 * j + 2], kB.x); ffma2(c1, qq1[4 * j + 3], kB.y);
        }
        float x0, x1, x2, x3;
        unpack2(a0, x0, x1); unpack2(a1, x2, x3);
        float p0 = (x0 + x1) + (x2 + x3);
        unpack2(c0, x0, x1); unpack2(c1, x2, x3);
        float p1 = (x0 + x1) + (x2 + x3);
        p0 += __shfl_xor_sync(0xFFFFFFFFu, p0, 1);
        p1 += __shfl_xor_sync(0xFFFFFFFFu, p1, 1);
        const float2 cb2 = *(const float2*)(cbb + m * 50);
        const float kr = krp[m];
        const float l0 = p0 * kr + cb2.x;
        const float l1 = p1 * kr + cb2.y;
        arow_own[m] = dh ? l1 : l0;
        mx0 = fmaxf(mx0, l0);
        mx1 = fmaxf(mx1, l1);
    }

    const float mxo = dh ? mx1 : mx0;
    float ss0 = 0.f, ss1 = 0.f;
    unsigned long long o20[8], o21[8];
    #pragma unroll
    for (int j = 0; j < 8; j++) { o20[j] = 0ULL; o21[j] = 0ULL; }
    #pragma unroll 7
    for (int m = 0; m < NTOK; m++) {
        const float eo = fexp(arow_own[m] - mxo);
        const float ex = __shfl_xor_sync(0xFFFFFFFFu, eo, 1);
        const float e0 = dh ? ex : eo;
        const float e1 = dh ? eo : ex;
        ss0 += e0; ss1 += e1;
        const ulonglong2* v4 = (const ulonglong2*)(Vs + m * 128 + h * 32 + dh * 16);
        const unsigned long long pp0 = pack2(e0, e0);
        const unsigned long long pp1 = pack2(e1, e1);
        #pragma unroll
        for (int j = 0; j < 2; j++) {
            const ulonglong2 vA = v4[2 * j], vB = v4[2 * j + 1];
            ffma2(o20[4 * j],     pp0, vA.x); ffma2(o20[4 * j + 1], pp0, vA.y);
            ffma2(o20[4 * j + 2], pp0, vB.x); ffma2(o20[4 * j + 3], pp0, vB.y);
            ffma2(o21[4 * j],     pp1, vA.x); ffma2(o21[4 * j + 1], pp1, vA.y);
            ffma2(o21[4 * j + 2], pp1, vB.x); ffma2(o21[4 * j + 3], pp1, vB.y);
        }
    }

    const float r0 = 1.0f / ss0;
    const float r1 = 1.0f / ss1;
    #pragma unroll
    for (int qi = 0; qi < 2; qi++) {
        const bool ok = qi ? v1 : act;
        if (!ok) continue;
        const unsigned long long* o2 = qi ? o21 : o20;
        const float rv = qi ? r1 : r0;
        const int q = q0 + qi;
        __half* dst = g_abig + ((size_t)b * NTOK + q) * KTOT + hg * 32 + dh * 16;
        uint32_t hv[8], lv[8];
        #pragma unroll
        for (int j = 0; j < 8; j++) {
            float x0, x1;
            unpack2(o2[j], x0, x1);
            x0 *= rv; x1 *= rv;
            const __half h0 = __float2half_rn(x0), h1 = __float2half_rn(x1);
            const __half l0 = __float2half_rn(x0 - __half2float(h0));
            const __half l1 = __float2half_rn(x1 - __half2float(h1));
            const __half2 hp = __halves2half2(h0, h1);
            const __half2 lp = __halves2half2(l0, l1);
            hv[j] = *(const uint32_t*)&hp;
            lv[j] = *(const uint32_t*)&lp;
        }
        const uint4 H0 = make_uint4(hv[0], hv[1], hv[2], hv[3]);
        const uint4 H1 = make_uint4(hv[4], hv[5], hv[6], hv[7]);
        const uint4 L0 = make_uint4(lv[0], lv[1], lv[2], lv[3]);
        const uint4 L1 = make_uint4(lv[4], lv[5], lv[6], lv[7]);
        *(uint4*)(dst)           = H0;
        *(uint4*)(dst + 8)       = H1;
        *(uint4*)(dst + 256)     = L0;
        *(uint4*)(dst + 256 + 8) = L1;
    }
}

// ---------------- launch ----------------------------------------------------------
extern "C" void kernel_launch(void* const* d_in, const int* in_sizes, int n_in,
                              void* d_out, int out_size)
{
    const float* x    = (const float*)d_in[0];
    const float* mask = (const float*)d_in[1];
    const float* qkvw = (const float*)d_in[2];
    const float* qb   = (const float*)d_in[3];
    const float* vb   = (const float*)d_in[4];
    const float* ls   = (const float*)d_in[5];
    const float* w1   = (const float*)d_in[6];
    const float* b1   = (const float*)d_in[7];
    const float* w2   = (const float*)d_in[8];
    const float* pw   = (const float*)d_in[9];
    const float* pb   = (const float*)d_in[10];
    const float* rct  = (const float*)d_in[11];
    const int*   rpi  = (const int*)d_in[12];
    float* out = (float*)d_out;

    const int attn_smem = ATT_SMEMF * 4;   // 90160 B
    cudaFuncSetAttribute(attn_kernel, cudaFuncAttributeMaxDynamicSharedMemorySize, attn_smem);

    const int nbias = (64 * 8 * 49 * 50 + 255) / 256;   // 3829 tail blocks

    prep_kernel<<<1, 256>>>(rct, w1, b1, w2, qb, vb);
    conv_w_kernel<<<1024, 256>>>(qkvw, pw);
    conv_a_kernel<<<25088, 256>>>(x);
    gemm_mma<<<6 * 784 + nbias, 256>>>(nullptr, nullptr, 0, rpi, mask);   // <- profiled
    attn_kernel<<<WNUM * 2, ATT_THREADS, attn_smem>>>(ls);
    gemm_mma<<<2 * 784, 256>>>(pb, out, 1, nullptr, nullptr);
}